// round 1
// baseline (speedup 1.0000x reference)
#include <cuda_runtime.h>

#define NFFT 16000
#define BT   1024

// Twiddle table: g_tw[t] = e^{-2*pi*i*t/N}
__device__ float2 g_tw[NFFT];

__global__ void tw_init_kernel() {
    int t = blockIdx.x * blockDim.x + threadIdx.x;
    if (t < NFFT) {
        double ang = -2.0 * 3.14159265358979323846 * (double)t / (double)NFFT;
        g_tw[t] = make_float2((float)cos(ang), (float)sin(ang));
    }
}

__device__ __forceinline__ float2 cadd(float2 a, float2 b) { return make_float2(a.x + b.x, a.y + b.y); }
__device__ __forceinline__ float2 csub(float2 a, float2 b) { return make_float2(a.x - b.x, a.y - b.y); }
__device__ __forceinline__ float2 cmul(float2 a, float2 b) {
    return make_float2(fmaf(a.x, b.x, -a.y * b.y), fmaf(a.x, b.y, a.y * b.x));
}
// multiply by (DIR * i)
template <int DIR>
__device__ __forceinline__ float2 cmuli(float2 a) {
    return (DIR > 0) ? make_float2(-a.y, a.x) : make_float2(a.y, -a.x);
}

template <int DIR>
__device__ __forceinline__ void dft2(float2* x) {
    float2 a = x[0], b = x[1];
    x[0] = cadd(a, b);
    x[1] = csub(a, b);
}

template <int DIR>
__device__ __forceinline__ void dft4(float2* x) {
    float2 t0 = cadd(x[0], x[2]);
    float2 t1 = csub(x[0], x[2]);
    float2 t2 = cadd(x[1], x[3]);
    float2 t3 = cmuli<DIR>(csub(x[1], x[3]));
    x[0] = cadd(t0, t2);
    x[2] = csub(t0, t2);
    x[1] = cadd(t1, t3);
    x[3] = csub(t1, t3);
}

template <int DIR>
__device__ __forceinline__ void dft5(float2* x) {
    const float c1 = 0.30901699437494742f;   // cos(2pi/5)
    const float c2 = -0.80901699437494745f;  // cos(4pi/5)
    const float s1 = 0.95105651629515357f;   // sin(2pi/5)
    const float s2 = 0.58778525229247313f;   // sin(4pi/5)
    float2 t1 = cadd(x[1], x[4]);
    float2 t2 = cadd(x[2], x[3]);
    float2 t3 = csub(x[1], x[4]);
    float2 t4 = csub(x[2], x[3]);
    float2 x0 = x[0];
    float2 a1 = make_float2(x0.x + c1 * t1.x + c2 * t2.x, x0.y + c1 * t1.y + c2 * t2.y);
    float2 a2 = make_float2(x0.x + c2 * t1.x + c1 * t2.x, x0.y + c2 * t1.y + c1 * t2.y);
    float2 b1 = make_float2(s1 * t3.x + s2 * t4.x, s1 * t3.y + s2 * t4.y);
    float2 b2 = make_float2(s2 * t3.x - s1 * t4.x, s2 * t3.y - s1 * t4.y);
    x[0] = make_float2(x0.x + t1.x + t2.x, x0.y + t1.y + t2.y);
    float2 ib1 = cmuli<DIR>(b1);
    float2 ib2 = cmuli<DIR>(b2);
    x[1] = cadd(a1, ib1);
    x[4] = csub(a1, ib1);
    x[2] = cadd(a2, ib2);
    x[3] = csub(a2, ib2);
}

template <int DIR>
__device__ __forceinline__ void dft8(float2* x) {
    float2 e[4] = {x[0], x[2], x[4], x[6]};
    float2 o[4] = {x[1], x[3], x[5], x[7]};
    dft4<DIR>(e);
    dft4<DIR>(o);
    const float H = 0.70710678118654752f;
    // w1 = e^{DIR*i*pi/4}, w2 = DIR*i, w3 = e^{DIR*3i*pi/4}
    float2 o1 = make_float2(H * (o[1].x - (float)DIR * o[1].y), H * (o[1].y + (float)DIR * o[1].x));
    float2 o2 = cmuli<DIR>(o[2]);
    float2 o3 = make_float2(H * (-o[3].x - (float)DIR * o[3].y), H * (-o[3].y + (float)DIR * o[3].x));
    x[0] = cadd(e[0], o[0]);
    x[4] = csub(e[0], o[0]);
    x[1] = cadd(e[1], o1);
    x[5] = csub(e[1], o1);
    x[2] = cadd(e[2], o2);
    x[6] = csub(e[2], o2);
    x[3] = cadd(e[3], o3);
    x[7] = csub(e[3], o3);
}

template <int R, int DIR>
__device__ __forceinline__ void dftR(float2* x) {
    if constexpr (R == 2) dft2<DIR>(x);
    else if constexpr (R == 4) dft4<DIR>(x);
    else if constexpr (R == 5) dft5<DIR>(x);
    else dft8<DIR>(x);
}

// One in-place Cooley-Tukey stage over the whole length-N row in SMEM.
// Forward (DIR=-1, DIF): butterfly DFT_R then twiddle w_NS^{j*n2}.
// Inverse (DIR=+1):      conj twiddle first, then DFT_R(+). (r-scale folded into 1/N at pointwise)
template <int R, int NS, int DIR>
__device__ __forceinline__ void fft_stage(float2* sm, int tid) {
    constexpr int m = NS / R;
    constexpr int K = NFFT / NS;
    constexpr int nb = NFFT / R;
    for (int u = tid; u < nb; u += BT) {
        int blk = u / m;
        int n2 = u - blk * m;
        int base = blk * NS + n2;
        float2 x[R];
#pragma unroll
        for (int j = 0; j < R; j++) x[j] = sm[base + j * m];
        if constexpr (DIR < 0) {
            dftR<R, DIR>(x);
            if constexpr (m > 1) {
#pragma unroll
                for (int j = 1; j < R; j++) x[j] = cmul(x[j], g_tw[j * n2 * K]);
            }
        } else {
            if constexpr (m > 1) {
#pragma unroll
                for (int j = 1; j < R; j++) {
                    float2 w = g_tw[j * n2 * K];
                    w.y = -w.y;
                    x[j] = cmul(x[j], w);
                }
            }
            dftR<R, DIR>(x);
        }
#pragma unroll
        for (int j = 0; j < R; j++) sm[base + j * m] = x[j];
    }
}

// Fused: scatter (packed img + i*seq) -> forward FFT -> Hermitian unpack + product
//        (in scrambled order) -> inverse FFT -> real part out.
__global__ void __launch_bounds__(BT) mcb_main_kernel(
    const float* __restrict__ img, const float* __restrict__ seq,
    const int* __restrict__ hv, const float* __restrict__ sv,
    float* __restrict__ out, int d) {
    extern __shared__ float2 sm[];
    const int b = blockIdx.x;
    const int tid = threadIdx.x;

    // zero sketch row
    for (int i = tid; i < NFFT; i += BT) sm[i] = make_float2(0.f, 0.f);
    __syncthreads();

    // scatter: sm[h[i]] += (img*s) + i*(seq*s)
    const float* irow = img + (size_t)b * d;
    const float* qrow = seq + (size_t)b * d;
    for (int i = tid; i < d; i += BT) {
        int h = hv[i];
        float s = sv[i];
        atomicAdd(&sm[h].x, irow[i] * s);
        atomicAdd(&sm[h].y, qrow[i] * s);
    }
    __syncthreads();

    // forward DIF FFT, radices 5,5,5,8,4,4  (output digit-scrambled)
    fft_stage<5, 16000, -1>(sm, tid); __syncthreads();
    fft_stage<5, 3200, -1>(sm, tid);  __syncthreads();
    fft_stage<5, 640, -1>(sm, tid);   __syncthreads();
    fft_stage<8, 128, -1>(sm, tid);   __syncthreads();
    fft_stage<4, 16, -1>(sm, tid);    __syncthreads();
    fft_stage<4, 4, -1>(sm, tid);     __syncthreads();

    // Hermitian unpack + pointwise product in scrambled domain.
    // Position p (digits d0..d5, strides 3200,640,128,16,4,1) holds frequency
    // f = d0 + 5 d1 + 25 d2 + 125 d3 + 1000 d4 + 4000 d5.
    const float invn = 1.0f / (float)NFFT;
    for (int p = tid; p < NFFT; p += BT) {
        int r = p;
        int d0 = r / 3200; r -= d0 * 3200;
        int d1 = r / 640;  r -= d1 * 640;
        int d2 = r / 128;  r -= d2 * 128;
        int d3 = r / 16;   r -= d3 * 16;
        int d4 = r / 4;
        int d5 = r - d4 * 4;
        int f = d0 + 5 * d1 + 25 * d2 + 125 * d3 + 1000 * d4 + 4000 * d5;
        int g = (NFFT - f) % NFFT;
        int e0 = g % 5; g /= 5;
        int e1 = g % 5; g /= 5;
        int e2 = g % 5; g /= 5;
        int e3 = g % 8; g /= 8;
        int e4 = g % 4; g /= 4;
        int e5 = g;
        int q = e0 * 3200 + e1 * 640 + e2 * 128 + e3 * 16 + e4 * 4 + e5;
        if (q < p) continue;  // each conjugate pair handled once (p==q when f==0 or f==N/2)
        float2 a = sm[p];   // C[f]
        float2 c = sm[q];   // C[N-f]
        // F_img = (C[f] + conj(C[N-f]))/2 ; F_seq = (C[f] - conj(C[N-f]))/(2i)
        float2 Fi = make_float2(0.5f * (a.x + c.x), 0.5f * (a.y - c.y));
        float2 Fs = make_float2(0.5f * (a.y + c.y), -0.5f * (a.x - c.x));
        float2 Z = cmul(Fi, Fs);
        Z.x *= invn;
        Z.y *= invn;
        sm[p] = Z;
        if (q != p) sm[q] = make_float2(Z.x, -Z.y);  // Z[N-f] = conj(Z[f])
    }
    __syncthreads();

    // inverse DIT FFT: stages in reverse order, scrambled in -> natural out
    fft_stage<4, 4, 1>(sm, tid);     __syncthreads();
    fft_stage<4, 16, 1>(sm, tid);    __syncthreads();
    fft_stage<8, 128, 1>(sm, tid);   __syncthreads();
    fft_stage<5, 640, 1>(sm, tid);   __syncthreads();
    fft_stage<5, 3200, 1>(sm, tid);  __syncthreads();
    fft_stage<5, 16000, 1>(sm, tid); __syncthreads();

    float* orow = out + (size_t)b * NFFT;
    for (int i = tid; i < NFFT; i += BT) orow[i] = sm[i].x;
}

extern "C" void kernel_launch(void* const* d_in, const int* in_sizes, int n_in,
                              void* d_out, int out_size) {
    const float* img = (const float*)d_in[0];
    const float* seq = (const float*)d_in[1];
    const int* hv = (const int*)d_in[2];
    const float* sv = (const float*)d_in[3];
    float* out = (float*)d_out;

    int d = in_sizes[2];          // feature dim (h_vec length)
    int B = in_sizes[0] / d;      // batch rows

    static_assert(NFFT == 16000, "radix plan assumes N=16000");

    cudaFuncSetAttribute(mcb_main_kernel, cudaFuncAttributeMaxDynamicSharedMemorySize,
                         NFFT * sizeof(float2));

    tw_init_kernel<<<(NFFT + 255) / 256, 256>>>();
    mcb_main_kernel<<<B, BT, NFFT * sizeof(float2)>>>(img, seq, hv, sv, out, d);
}

// round 2
// speedup vs baseline: 1.5043x; 1.5043x over previous
#include <cuda_runtime.h>

#define NFFT 16000
#define BT   1024

// Radix plan (forward DIF order): 4, 4, 8, 5, 5, 5
//   stage strides m: 4000, 1000, 125, 25, 5, 1  (no small power-of-two strides
//   -> bank-conflict-free late stages)
// Scrambled position p = 4000*d0 + 1000*d1 + 125*d2 + 25*d3 + 5*d4 + d5
// holds frequency      f = d0 + 4*d1 + 16*d2 + 128*d3 + 640*d4 + 3200*d5.

__device__ float2 g_tw[NFFT];      // e^{-2*pi*i*t/N}
__device__ int    g_partner[NFFT]; // scrambled position of frequency N-f

__global__ void init_tables_kernel() {
    int p = blockIdx.x * blockDim.x + threadIdx.x;
    if (p >= NFFT) return;
    double ang = -2.0 * 3.14159265358979323846 * (double)p / (double)NFFT;
    g_tw[p] = make_float2((float)cos(ang), (float)sin(ang));

    int r = p;
    int d0 = r / 4000; r -= d0 * 4000;
    int d1 = r / 1000; r -= d1 * 1000;
    int d2 = r / 125;  r -= d2 * 125;
    int d3 = r / 25;   r -= d3 * 25;
    int d4 = r / 5;
    int d5 = r - d4 * 5;
    int f = d0 + 4 * d1 + 16 * d2 + 128 * d3 + 640 * d4 + 3200 * d5;
    int g = (NFFT - f) % NFFT;
    int e0 = g % 4; g /= 4;
    int e1 = g % 4; g /= 4;
    int e2 = g % 8; g /= 8;
    int e3 = g % 5; g /= 5;
    int e4 = g % 5; g /= 5;
    int e5 = g;
    g_partner[p] = e0 * 4000 + e1 * 1000 + e2 * 125 + e3 * 25 + e4 * 5 + e5;
}

__device__ __forceinline__ float2 cadd(float2 a, float2 b) { return make_float2(a.x + b.x, a.y + b.y); }
__device__ __forceinline__ float2 csub(float2 a, float2 b) { return make_float2(a.x - b.x, a.y - b.y); }
__device__ __forceinline__ float2 cmul(float2 a, float2 b) {
    return make_float2(fmaf(a.x, b.x, -a.y * b.y), fmaf(a.x, b.y, a.y * b.x));
}
template <int DIR>
__device__ __forceinline__ float2 cmuli(float2 a) {   // multiply by DIR*i
    return (DIR > 0) ? make_float2(-a.y, a.x) : make_float2(a.y, -a.x);
}

template <int DIR>
__device__ __forceinline__ void dft4(float2* x) {
    float2 t0 = cadd(x[0], x[2]);
    float2 t1 = csub(x[0], x[2]);
    float2 t2 = cadd(x[1], x[3]);
    float2 t3 = cmuli<DIR>(csub(x[1], x[3]));
    x[0] = cadd(t0, t2);
    x[2] = csub(t0, t2);
    x[1] = cadd(t1, t3);
    x[3] = csub(t1, t3);
}

template <int DIR>
__device__ __forceinline__ void dft5(float2* x) {
    const float c1 = 0.30901699437494742f;
    const float c2 = -0.80901699437494745f;
    const float s1 = 0.95105651629515357f;
    const float s2 = 0.58778525229247313f;
    float2 t1 = cadd(x[1], x[4]);
    float2 t2 = cadd(x[2], x[3]);
    float2 t3 = csub(x[1], x[4]);
    float2 t4 = csub(x[2], x[3]);
    float2 x0 = x[0];
    float2 a1 = make_float2(x0.x + c1 * t1.x + c2 * t2.x, x0.y + c1 * t1.y + c2 * t2.y);
    float2 a2 = make_float2(x0.x + c2 * t1.x + c1 * t2.x, x0.y + c2 * t1.y + c1 * t2.y);
    float2 b1 = make_float2(s1 * t3.x + s2 * t4.x, s1 * t3.y + s2 * t4.y);
    float2 b2 = make_float2(s2 * t3.x - s1 * t4.x, s2 * t3.y - s1 * t4.y);
    x[0] = make_float2(x0.x + t1.x + t2.x, x0.y + t1.y + t2.y);
    float2 ib1 = cmuli<DIR>(b1);
    float2 ib2 = cmuli<DIR>(b2);
    x[1] = cadd(a1, ib1);
    x[4] = csub(a1, ib1);
    x[2] = cadd(a2, ib2);
    x[3] = csub(a2, ib2);
}

template <int DIR>
__device__ __forceinline__ void dft8(float2* x) {
    float2 e[4] = {x[0], x[2], x[4], x[6]};
    float2 o[4] = {x[1], x[3], x[5], x[7]};
    dft4<DIR>(e);
    dft4<DIR>(o);
    const float H = 0.70710678118654752f;
    float2 o1 = make_float2(H * (o[1].x - (float)DIR * o[1].y), H * (o[1].y + (float)DIR * o[1].x));
    float2 o2 = cmuli<DIR>(o[2]);
    float2 o3 = make_float2(H * (-o[3].x - (float)DIR * o[3].y), H * (-o[3].y + (float)DIR * o[3].x));
    x[0] = cadd(e[0], o[0]);
    x[4] = csub(e[0], o[0]);
    x[1] = cadd(e[1], o1);
    x[5] = csub(e[1], o1);
    x[2] = cadd(e[2], o2);
    x[6] = csub(e[2], o2);
    x[3] = cadd(e[3], o3);
    x[7] = csub(e[3], o3);
}

template <int R, int DIR>
__device__ __forceinline__ void dftR(float2* x) {
    if constexpr (R == 4) dft4<DIR>(x);
    else if constexpr (R == 5) dft5<DIR>(x);
    else dft8<DIR>(x);
}

// One in-place Cooley-Tukey stage over the length-N row in SMEM.
// Forward (DIR=-1, DIF): DFT_R then twiddle w^{j*n2*K}.
// Inverse (DIR=+1):      conj twiddle, then DFT_R(+).
// Only w^1 is loaded; higher powers computed by complex mults (keeps twiddle
// traffic off the L1 pipe, which is the binding resource).
template <int R, int NS, int DIR>
__device__ __forceinline__ void fft_stage(float2* sm, int tid) {
    constexpr int m = NS / R;
    constexpr int K = NFFT / NS;
    constexpr int nb = NFFT / R;
    for (int u = tid; u < nb; u += BT) {
        int blk = u / m;
        int n2 = u - blk * m;
        int base = blk * NS + n2;
        float2 x[R];
#pragma unroll
        for (int j = 0; j < R; j++) x[j] = sm[base + j * m];
        if constexpr (m > 1) {
            float2 w[R];
            w[1] = g_tw[n2 * K];
            if constexpr (DIR > 0) w[1].y = -w[1].y;
            if constexpr (R >= 4) {
                w[2] = cmul(w[1], w[1]);
                w[3] = cmul(w[2], w[1]);
            }
            if constexpr (R == 5) w[4] = cmul(w[2], w[2]);
            if constexpr (R == 8) {
                w[4] = cmul(w[2], w[2]);
                w[5] = cmul(w[2], w[3]);
                w[6] = cmul(w[3], w[3]);
                w[7] = cmul(w[3], w[4]);
            }
            if constexpr (DIR < 0) {
                dftR<R, DIR>(x);
#pragma unroll
                for (int j = 1; j < R; j++) x[j] = cmul(x[j], w[j]);
            } else {
#pragma unroll
                for (int j = 1; j < R; j++) x[j] = cmul(x[j], w[j]);
                dftR<R, DIR>(x);
            }
        } else {
            dftR<R, DIR>(x);
        }
#pragma unroll
        for (int j = 0; j < R; j++) sm[base + j * m] = x[j];
    }
}

__global__ void __launch_bounds__(BT) mcb_main_kernel(
    const float* __restrict__ img, const float* __restrict__ seq,
    const int* __restrict__ hv, const float* __restrict__ sv,
    float* __restrict__ out, int d) {
    extern __shared__ float2 sm[];
    const int b = blockIdx.x;
    const int tid = threadIdx.x;

    // zero sketch row (vectorized: 8000 float4 stores)
    float4* sm4 = (float4*)sm;
    for (int i = tid; i < NFFT / 2; i += BT) sm4[i] = make_float4(0.f, 0.f, 0.f, 0.f);
    __syncthreads();

    // scatter: sm[h[i]] += (img*s) + i*(seq*s)
    const float* irow = img + (size_t)b * d;
    const float* qrow = seq + (size_t)b * d;
    for (int i = tid; i < d; i += BT) {
        int h = hv[i];
        float s = sv[i];
        atomicAdd(&sm[h].x, irow[i] * s);
        atomicAdd(&sm[h].y, qrow[i] * s);
    }
    __syncthreads();

    // forward DIF FFT, radices 4,4,8,5,5,5  (output digit-scrambled)
    fft_stage<4, 16000, -1>(sm, tid); __syncthreads();
    fft_stage<4, 4000, -1>(sm, tid);  __syncthreads();
    fft_stage<8, 1000, -1>(sm, tid);  __syncthreads();
    fft_stage<5, 125, -1>(sm, tid);   __syncthreads();
    fft_stage<5, 25, -1>(sm, tid);    __syncthreads();
    fft_stage<5, 5, -1>(sm, tid);     __syncthreads();

    // Hermitian unpack + pointwise product in scrambled domain.
    const float scale = 0.25f / (float)NFFT;  // two 0.5 unpack factors + 1/N ifft
    for (int p = tid; p < NFFT; p += BT) {
        int q = g_partner[p];
        if (q < p) continue;  // each conjugate pair once (p==q at f==0 / N/2)
        float2 a = sm[p];     // C[f]
        float2 c = sm[q];     // C[N-f]
        // F_img = (C[f] + conj(C[N-f]))/2 ; F_seq = (C[f] - conj(C[N-f]))/(2i)
        float2 Fi = make_float2(a.x + c.x, a.y - c.y);
        float2 Fs = make_float2(a.y + c.y, -(a.x - c.x));
        float2 Z = cmul(Fi, Fs);
        Z.x *= scale;
        Z.y *= scale;
        sm[p] = Z;
        if (q != p) sm[q] = make_float2(Z.x, -Z.y);  // Z[N-f] = conj(Z[f])
    }
    __syncthreads();

    // inverse DIT FFT: reverse stage order, scrambled in -> natural out
    fft_stage<5, 5, 1>(sm, tid);     __syncthreads();
    fft_stage<5, 25, 1>(sm, tid);    __syncthreads();
    fft_stage<5, 125, 1>(sm, tid);   __syncthreads();
    fft_stage<8, 1000, 1>(sm, tid);  __syncthreads();
    fft_stage<4, 4000, 1>(sm, tid);  __syncthreads();
    fft_stage<4, 16000, 1>(sm, tid); __syncthreads();

    // vectorized real-part writeout: LDS.128 (two complex) -> STG.64 (two floats)
    float2* orow2 = (float2*)(out + (size_t)b * NFFT);
    for (int i = tid; i < NFFT / 2; i += BT) {
        float4 v = sm4[i];
        orow2[i] = make_float2(v.x, v.z);
    }
}

extern "C" void kernel_launch(void* const* d_in, const int* in_sizes, int n_in,
                              void* d_out, int out_size) {
    const float* img = (const float*)d_in[0];
    const float* seq = (const float*)d_in[1];
    const int* hv = (const int*)d_in[2];
    const float* sv = (const float*)d_in[3];
    float* out = (float*)d_out;

    int d = in_sizes[2];       // feature dim (h_vec length)
    int B = in_sizes[0] / d;   // batch rows

    static_assert(NFFT == 16000, "radix plan assumes N=16000");

    cudaFuncSetAttribute(mcb_main_kernel, cudaFuncAttributeMaxDynamicSharedMemorySize,
                         NFFT * sizeof(float2));

    init_tables_kernel<<<(NFFT + 255) / 256, 256>>>();
    mcb_main_kernel<<<B, BT, NFFT * sizeof(float2)>>>(img, seq, hv, sv, out, d);
}

// round 3
// speedup vs baseline: 1.9590x; 1.3023x over previous
#include <cuda_runtime.h>

#define NFFT 16000
#define BT   800
// bank-conflict padding: element i lives at sm[PHI(i)]
#define PHI(i) ((i) + ((i) / 80))
#define SMPAD (NFFT + NFFT / 80)   // 16200 float2 = 129600 B

// Radix plan (forward DIF order): 16, 10, 10, 10
//   stage strides m: 1000, 100, 10, 1
// Scrambled position p = 1000*d0 + 100*d1 + 10*d2 + d3  (d0<16, d1..d3<10)
// holds frequency      f = d0 + 16*d1 + 160*d2 + 1600*d3.

__device__ float2 g_tw[NFFT];      // e^{-2*pi*i*t/N}
__device__ int    g_partner[NFFT]; // scrambled position of frequency N-f

__global__ void init_tables_kernel() {
    int p = blockIdx.x * blockDim.x + threadIdx.x;
    if (p >= NFFT) return;
    double ang = -2.0 * 3.14159265358979323846 * (double)p / (double)NFFT;
    g_tw[p] = make_float2((float)cos(ang), (float)sin(ang));

    int d0 = p / 1000;
    int r = p - d0 * 1000;
    int d1 = r / 100;  r -= d1 * 100;
    int d2 = r / 10;
    int d3 = r - d2 * 10;
    int f = d0 + 16 * d1 + 160 * d2 + 1600 * d3;
    int g = (NFFT - f) % NFFT;
    int e0 = g % 16;
    int g2 = g / 16;
    int e1 = g2 % 10;
    int e2 = (g2 / 10) % 10;
    int e3 = g2 / 100;
    g_partner[p] = 1000 * e0 + 100 * e1 + 10 * e2 + e3;
}

__device__ __forceinline__ float2 cadd(float2 a, float2 b) { return make_float2(a.x + b.x, a.y + b.y); }
__device__ __forceinline__ float2 csub(float2 a, float2 b) { return make_float2(a.x - b.x, a.y - b.y); }
__device__ __forceinline__ float2 cmul(float2 a, float2 b) {
    return make_float2(fmaf(a.x, b.x, -a.y * b.y), fmaf(a.x, b.y, a.y * b.x));
}
__device__ __forceinline__ float2 cmulc(float2 a, float cr, float ci) {
    return make_float2(fmaf(a.x, cr, -a.y * ci), fmaf(a.x, ci, a.y * cr));
}
template <int DIR>
__device__ __forceinline__ float2 cmuli(float2 a) {   // multiply by DIR*i
    return (DIR > 0) ? make_float2(-a.y, a.x) : make_float2(a.y, -a.x);
}

template <int DIR>
__device__ __forceinline__ void dft4(float2* x) {
    float2 t0 = cadd(x[0], x[2]);
    float2 t1 = csub(x[0], x[2]);
    float2 t2 = cadd(x[1], x[3]);
    float2 t3 = cmuli<DIR>(csub(x[1], x[3]));
    x[0] = cadd(t0, t2);
    x[2] = csub(t0, t2);
    x[1] = cadd(t1, t3);
    x[3] = csub(t1, t3);
}

template <int DIR>
__device__ __forceinline__ void dft5(float2* x) {
    const float c1 = 0.30901699437494742f;
    const float c2 = -0.80901699437494745f;
    const float s1 = 0.95105651629515357f;
    const float s2 = 0.58778525229247313f;
    float2 t1 = cadd(x[1], x[4]);
    float2 t2 = cadd(x[2], x[3]);
    float2 t3 = csub(x[1], x[4]);
    float2 t4 = csub(x[2], x[3]);
    float2 x0 = x[0];
    float2 a1 = make_float2(x0.x + c1 * t1.x + c2 * t2.x, x0.y + c1 * t1.y + c2 * t2.y);
    float2 a2 = make_float2(x0.x + c2 * t1.x + c1 * t2.x, x0.y + c2 * t1.y + c1 * t2.y);
    float2 b1 = make_float2(s1 * t3.x + s2 * t4.x, s1 * t3.y + s2 * t4.y);
    float2 b2 = make_float2(s2 * t3.x - s1 * t4.x, s2 * t3.y - s1 * t4.y);
    x[0] = make_float2(x0.x + t1.x + t2.x, x0.y + t1.y + t2.y);
    float2 ib1 = cmuli<DIR>(b1);
    float2 ib2 = cmuli<DIR>(b2);
    x[1] = cadd(a1, ib1);
    x[4] = csub(a1, ib1);
    x[2] = cadd(a2, ib2);
    x[3] = csub(a2, ib2);
}

// 16-point DFT = 4x4 Cooley-Tukey, fully in registers.
template <int DIR>
__device__ __forceinline__ void dft16(float2* x) {
    const float C1 = 0.92387953251128674f;  // cos(pi/8)
    const float S1 = 0.38268343236508978f;  // sin(pi/8)
    const float C2 = 0.70710678118654752f;  // cos(pi/4)
    const float D = (float)DIR;
    float2 y[16];
#pragma unroll
    for (int n2 = 0; n2 < 4; n2++) {
        float2 t[4] = {x[n2], x[n2 + 4], x[n2 + 8], x[n2 + 12]};
        dft4<DIR>(t);
        if (n2 == 1) {
            t[1] = cmulc(t[1], C1, D * S1);
            t[2] = cmulc(t[2], C2, D * C2);
            t[3] = cmulc(t[3], S1, D * C1);
        } else if (n2 == 2) {
            t[1] = cmulc(t[1], C2, D * C2);
            t[2] = cmuli<DIR>(t[2]);
            t[3] = cmulc(t[3], -C2, D * C2);
        } else if (n2 == 3) {
            t[1] = cmulc(t[1], S1, D * C1);
            t[2] = cmulc(t[2], -C2, D * C2);
            t[3] = cmulc(t[3], -C1, -D * S1);
        }
        y[0 + n2] = t[0];
        y[4 + n2] = t[1];
        y[8 + n2] = t[2];
        y[12 + n2] = t[3];
    }
#pragma unroll
    for (int k1 = 0; k1 < 4; k1++) {
        float2 t[4] = {y[k1 * 4 + 0], y[k1 * 4 + 1], y[k1 * 4 + 2], y[k1 * 4 + 3]};
        dft4<DIR>(t);
        x[k1 + 0] = t[0];
        x[k1 + 4] = t[1];
        x[k1 + 8] = t[2];
        x[k1 + 12] = t[3];
    }
}

// 10-point DFT = 2x5 Cooley-Tukey, in registers.
template <int DIR>
__device__ __forceinline__ void dft10(float2* x) {
    const float C36 = 0.80901699437494742f;
    const float S36 = 0.58778525229247313f;
    const float C72 = 0.30901699437494742f;
    const float S72 = 0.95105651629515357f;
    const float D = (float)DIR;
    float2 a[5], c[5];
#pragma unroll
    for (int n2 = 0; n2 < 5; n2++) {
        a[n2] = cadd(x[n2], x[n2 + 5]);
        c[n2] = csub(x[n2], x[n2 + 5]);
    }
    c[1] = cmulc(c[1], C36, D * S36);
    c[2] = cmulc(c[2], C72, D * S72);
    c[3] = cmulc(c[3], -C72, D * S72);
    c[4] = cmulc(c[4], -C36, D * S36);
    dft5<DIR>(a);
    dft5<DIR>(c);
    x[0] = a[0]; x[2] = a[1]; x[4] = a[2]; x[6] = a[3]; x[8] = a[4];
    x[1] = c[0]; x[3] = c[1]; x[5] = c[2]; x[7] = c[3]; x[9] = c[4];
}

template <int R, int DIR>
__device__ __forceinline__ void dftR(float2* x) {
    if constexpr (R == 16) dft16<DIR>(x);
    else if constexpr (R == 10) dft10<DIR>(x);
    else if constexpr (R == 5) dft5<DIR>(x);
    else dft4<DIR>(x);
}

// Apply stage twiddles x[j] *= w1^j, powers built with depth<=3 products.
template <int R>
__device__ __forceinline__ void apply_twiddles(float2* x, float2 w1) {
    float2 w2 = cmul(w1, w1);
    float2 w3 = cmul(w2, w1);
    float2 w4 = cmul(w2, w2);
    x[1] = cmul(x[1], w1);
    x[2] = cmul(x[2], w2);
    x[3] = cmul(x[3], w3);
    x[4] = cmul(x[4], w4);
    if constexpr (R == 10) {
        float2 w5 = cmul(w4, w1);
        x[5] = cmul(x[5], w5);
        x[6] = cmul(x[6], cmul(w5, w1));
        x[7] = cmul(x[7], cmul(w5, w2));
        x[8] = cmul(x[8], cmul(w5, w3));
        x[9] = cmul(x[9], cmul(w5, w4));
    }
    if constexpr (R == 16) {
        float2 w5 = cmul(w4, w1);
        float2 w6 = cmul(w4, w2);
        float2 w7 = cmul(w4, w3);
        float2 w8 = cmul(w4, w4);
        x[5] = cmul(x[5], w5);
        x[6] = cmul(x[6], w6);
        x[7] = cmul(x[7], w7);
        x[8] = cmul(x[8], w8);
        x[9] = cmul(x[9], cmul(w8, w1));
        x[10] = cmul(x[10], cmul(w8, w2));
        x[11] = cmul(x[11], cmul(w8, w3));
        x[12] = cmul(x[12], cmul(w8, w4));
        x[13] = cmul(x[13], cmul(w8, w5));
        x[14] = cmul(x[14], cmul(w8, w6));
        x[15] = cmul(x[15], cmul(w8, w7));
    }
}

// One in-place CT stage. Forward (DIR=-1, DIF): DFT_R then twiddle.
// Inverse (DIR=+1, DIT): conj twiddle then DFT_R.
// TO_GMEM: store real parts directly to gout (natural index) instead of smem.
template <int R, int NS, int DIR, bool TO_GMEM>
__device__ __forceinline__ void fft_stage(float2* sm, int tid, float* gout) {
    constexpr int m = NS / R;
    constexpr int K = NFFT / NS;
    constexpr int nb = NFFT / R;
    for (int u = tid; u < nb; u += BT) {
        int blk = u / m;
        int n2 = u - blk * m;
        int base = blk * NS + n2;
        float2 x[R];
#pragma unroll
        for (int j = 0; j < R; j++) {
            int idx = base + j * m;
            x[j] = sm[PHI(idx)];
        }
        if constexpr (m > 1) {
            float2 w1 = g_tw[n2 * K];
            if constexpr (DIR > 0) w1.y = -w1.y;
            if constexpr (DIR < 0) {
                dftR<R, DIR>(x);
                apply_twiddles<R>(x, w1);
            } else {
                apply_twiddles<R>(x, w1);
                dftR<R, DIR>(x);
            }
        } else {
            dftR<R, DIR>(x);
        }
#pragma unroll
        for (int j = 0; j < R; j++) {
            int idx = base + j * m;
            if constexpr (TO_GMEM) gout[idx] = x[j].x;
            else sm[PHI(idx)] = x[j];
        }
    }
}

__global__ void __launch_bounds__(BT) mcb_main_kernel(
    const float* __restrict__ img, const float* __restrict__ seq,
    const int* __restrict__ hv, const float* __restrict__ sv,
    float* __restrict__ out, int d) {
    extern __shared__ float2 sm[];
    const int b = blockIdx.x;
    const int tid = threadIdx.x;

    // zero padded sketch row (float4 vectorized)
    float4* sm4 = (float4*)sm;
    for (int i = tid; i < SMPAD / 2; i += BT) sm4[i] = make_float4(0.f, 0.f, 0.f, 0.f);
    __syncthreads();

    // scatter: sm[h[i]] += (img*s) + i*(seq*s)
    const float* irow = img + (size_t)b * d;
    const float* qrow = seq + (size_t)b * d;
    for (int i = tid; i < d; i += BT) {
        int h = PHI(hv[i]);
        float s = sv[i];
        atomicAdd(&sm[h].x, irow[i] * s);
        atomicAdd(&sm[h].y, qrow[i] * s);
    }
    __syncthreads();

    float* orow = out + (size_t)b * NFFT;

    // forward DIF FFT, radices 16,10,10,10 (output digit-scrambled)
    fft_stage<16, 16000, -1, false>(sm, tid, orow); __syncthreads();
    fft_stage<10, 1000, -1, false>(sm, tid, orow);  __syncthreads();
    fft_stage<10, 100, -1, false>(sm, tid, orow);   __syncthreads();
    fft_stage<10, 10, -1, false>(sm, tid, orow);    __syncthreads();

    // Hermitian unpack + pointwise product in scrambled domain
    const float scale = 0.25f / (float)NFFT;  // two 0.5 unpack factors + 1/N
    for (int p = tid; p < NFFT; p += BT) {
        int q = g_partner[p];
        if (q < p) continue;  // each conjugate pair once (p==q at f==0 / N/2)
        int pp = PHI(p), qq = PHI(q);
        float2 a = sm[pp];  // C[f]
        float2 c = sm[qq];  // C[N-f]
        float2 Fi = make_float2(a.x + c.x, a.y - c.y);
        float2 Fs = make_float2(a.y + c.y, -(a.x - c.x));
        float2 Z = cmul(Fi, Fs);
        Z.x *= scale;
        Z.y *= scale;
        sm[pp] = Z;
        if (qq != pp) sm[qq] = make_float2(Z.x, -Z.y);
    }
    __syncthreads();

    // inverse DIT FFT: reverse stage order, scrambled in -> natural out;
    // final stage streams real parts straight to GMEM.
    fft_stage<10, 10, 1, false>(sm, tid, orow);    __syncthreads();
    fft_stage<10, 100, 1, false>(sm, tid, orow);   __syncthreads();
    fft_stage<10, 1000, 1, false>(sm, tid, orow);  __syncthreads();
    fft_stage<16, 16000, 1, true>(sm, tid, orow);
}

extern "C" void kernel_launch(void* const* d_in, const int* in_sizes, int n_in,
                              void* d_out, int out_size) {
    const float* img = (const float*)d_in[0];
    const float* seq = (const float*)d_in[1];
    const int* hv = (const int*)d_in[2];
    const float* sv = (const float*)d_in[3];
    float* out = (float*)d_out;

    int d = in_sizes[2];       // feature dim (h_vec length)
    int B = in_sizes[0] / d;   // batch rows

    static_assert(NFFT == 16000, "radix plan assumes N=16000");

    cudaFuncSetAttribute(mcb_main_kernel, cudaFuncAttributeMaxDynamicSharedMemorySize,
                         SMPAD * sizeof(float2));

    init_tables_kernel<<<(NFFT + 255) / 256, 256>>>();
    mcb_main_kernel<<<B, BT, SMPAD * sizeof(float2)>>>(img, seq, hv, sv, out, d);
}

// round 4
// speedup vs baseline: 2.2347x; 1.1408x over previous
#include <cuda_runtime.h>

#define NFFT 16000
#define BT   800
// bank padding: element i lives at sm[PHI(i)]; +6 complex per 100 keeps every
// strided stage's wavefront addresses advancing +16B mod 128 (conflict-free).
#define PHI(i) ((i) + 6 * ((i) / 100))
#define SMPAD (NFFT + 6 * (NFFT / 100))   // 16960 float2 = 135680 B

// Radix plan (forward DIF): 16, 10, 10, 10  -> strides m: 1000, 100, 10, 1
// Scrambled p = 1000*d0 + 100*d1 + 10*d2 + d3 holds f = d0 + 16*d1 + 160*d2 + 1600*d3.
// Block = p/10 (digits d0,d1,d2; freq part f0 = d0+16*d1+160*d2); Hermitian
// partner of block(f0) is block(1600-f0), elementwise t <-> 9-t.

__device__ float2 g_tw[NFFT];   // e^{-2*pi*i*t/N}
__device__ int    g_pairs[BT];  // u<799: blocks for f0=u+1 ; u=799: special (f0=0 & f0=800)

__device__ __forceinline__ int block_of(int f0) {
    return 100 * (f0 % 16) + 10 * ((f0 / 16) % 10) + (f0 / 160);
}

__global__ void init_tables_kernel() {
    int p = blockIdx.x * blockDim.x + threadIdx.x;
    if (p < NFFT) {
        double ang = -2.0 * 3.14159265358979323846 * (double)p / (double)NFFT;
        g_tw[p] = make_float2((float)cos(ang), (float)sin(ang));
    }
    if (p < 799) {
        int f0 = p + 1;
        g_pairs[p] = block_of(f0) | (block_of(1600 - f0) << 16);
    } else if (p == 799) {
        g_pairs[p] = block_of(0) | (block_of(800) << 16) | (1 << 30);  // special
    }
}

__device__ __forceinline__ float2 cadd(float2 a, float2 b) { return make_float2(a.x + b.x, a.y + b.y); }
__device__ __forceinline__ float2 csub(float2 a, float2 b) { return make_float2(a.x - b.x, a.y - b.y); }
__device__ __forceinline__ float2 cmul(float2 a, float2 b) {
    return make_float2(fmaf(a.x, b.x, -a.y * b.y), fmaf(a.x, b.y, a.y * b.x));
}
__device__ __forceinline__ float2 cmulc(float2 a, float cr, float ci) {
    return make_float2(fmaf(a.x, cr, -a.y * ci), fmaf(a.x, ci, a.y * cr));
}
template <int DIR>
__device__ __forceinline__ float2 cmuli(float2 a) {   // * (DIR*i)
    return (DIR > 0) ? make_float2(-a.y, a.x) : make_float2(a.y, -a.x);
}

template <int DIR>
__device__ __forceinline__ void dft4(float2* x) {
    float2 t0 = cadd(x[0], x[2]);
    float2 t1 = csub(x[0], x[2]);
    float2 t2 = cadd(x[1], x[3]);
    float2 t3 = cmuli<DIR>(csub(x[1], x[3]));
    x[0] = cadd(t0, t2);
    x[2] = csub(t0, t2);
    x[1] = cadd(t1, t3);
    x[3] = csub(t1, t3);
}

template <int DIR>
__device__ __forceinline__ void dft5(float2* x) {
    const float c1 = 0.30901699437494742f;
    const float c2 = -0.80901699437494745f;
    const float s1 = 0.95105651629515357f;
    const float s2 = 0.58778525229247313f;
    float2 t1 = cadd(x[1], x[4]);
    float2 t2 = cadd(x[2], x[3]);
    float2 t3 = csub(x[1], x[4]);
    float2 t4 = csub(x[2], x[3]);
    float2 x0 = x[0];
    float2 a1 = make_float2(x0.x + c1 * t1.x + c2 * t2.x, x0.y + c1 * t1.y + c2 * t2.y);
    float2 a2 = make_float2(x0.x + c2 * t1.x + c1 * t2.x, x0.y + c2 * t1.y + c1 * t2.y);
    float2 b1 = make_float2(s1 * t3.x + s2 * t4.x, s1 * t3.y + s2 * t4.y);
    float2 b2 = make_float2(s2 * t3.x - s1 * t4.x, s2 * t3.y - s1 * t4.y);
    x[0] = make_float2(x0.x + t1.x + t2.x, x0.y + t1.y + t2.y);
    float2 ib1 = cmuli<DIR>(b1);
    float2 ib2 = cmuli<DIR>(b2);
    x[1] = cadd(a1, ib1);
    x[4] = csub(a1, ib1);
    x[2] = cadd(a2, ib2);
    x[3] = csub(a2, ib2);
}

// 10-point DFT = 2x5 CT, x accessed with compile-time stride S.
template <int DIR, int S>
__device__ __forceinline__ void dft10s(float2* x) {
    const float C36 = 0.80901699437494742f;
    const float S36 = 0.58778525229247313f;
    const float C72 = 0.30901699437494742f;
    const float S72 = 0.95105651629515357f;
    const float D = (float)DIR;
    float2 a[5], c[5];
#pragma unroll
    for (int k = 0; k < 5; k++) {
        a[k] = cadd(x[k * S], x[(k + 5) * S]);
        c[k] = csub(x[k * S], x[(k + 5) * S]);
    }
    c[1] = cmulc(c[1], C36, D * S36);
    c[2] = cmulc(c[2], C72, D * S72);
    c[3] = cmulc(c[3], -C72, D * S72);
    c[4] = cmulc(c[4], -C36, D * S36);
    dft5<DIR>(a);
    dft5<DIR>(c);
    x[0 * S] = a[0]; x[2 * S] = a[1]; x[4 * S] = a[2]; x[6 * S] = a[3]; x[8 * S] = a[4];
    x[1 * S] = c[0]; x[3 * S] = c[1]; x[5 * S] = c[2]; x[7 * S] = c[3]; x[9 * S] = c[4];
}

// 16-point DFT = 4x4 CT (contiguous).
template <int DIR>
__device__ __forceinline__ void dft16(float2* x) {
    const float C1 = 0.92387953251128674f;
    const float S1 = 0.38268343236508978f;
    const float C2 = 0.70710678118654752f;
    const float D = (float)DIR;
    float2 y[16];
#pragma unroll
    for (int n2 = 0; n2 < 4; n2++) {
        float2 t[4] = {x[n2], x[n2 + 4], x[n2 + 8], x[n2 + 12]};
        dft4<DIR>(t);
        if (n2 == 1) {
            t[1] = cmulc(t[1], C1, D * S1);
            t[2] = cmulc(t[2], C2, D * C2);
            t[3] = cmulc(t[3], S1, D * C1);
        } else if (n2 == 2) {
            t[1] = cmulc(t[1], C2, D * C2);
            t[2] = cmuli<DIR>(t[2]);
            t[3] = cmulc(t[3], -C2, D * C2);
        } else if (n2 == 3) {
            t[1] = cmulc(t[1], S1, D * C1);
            t[2] = cmulc(t[2], -C2, D * C2);
            t[3] = cmulc(t[3], -C1, -D * S1);
        }
        y[0 + n2] = t[0]; y[4 + n2] = t[1]; y[8 + n2] = t[2]; y[12 + n2] = t[3];
    }
#pragma unroll
    for (int k1 = 0; k1 < 4; k1++) {
        float2 t[4] = {y[k1 * 4 + 0], y[k1 * 4 + 1], y[k1 * 4 + 2], y[k1 * 4 + 3]};
        dft4<DIR>(t);
        x[k1 + 0] = t[0]; x[k1 + 4] = t[1]; x[k1 + 8] = t[2]; x[k1 + 12] = t[3];
    }
}

template <int S>
__device__ __forceinline__ void apply_tw10(float2* x, float2 w1) {
    float2 w2 = cmul(w1, w1);
    float2 w3 = cmul(w2, w1);
    float2 w4 = cmul(w2, w2);
    float2 w5 = cmul(w4, w1);
    x[1 * S] = cmul(x[1 * S], w1);
    x[2 * S] = cmul(x[2 * S], w2);
    x[3 * S] = cmul(x[3 * S], w3);
    x[4 * S] = cmul(x[4 * S], w4);
    x[5 * S] = cmul(x[5 * S], w5);
    x[6 * S] = cmul(x[6 * S], cmul(w5, w1));
    x[7 * S] = cmul(x[7 * S], cmul(w5, w2));
    x[8 * S] = cmul(x[8 * S], cmul(w5, w3));
    x[9 * S] = cmul(x[9 * S], cmul(w5, w4));
}

__device__ __forceinline__ void apply_tw16(float2* x, float2 w1) {
    float2 w2 = cmul(w1, w1);
    float2 w3 = cmul(w2, w1);
    float2 w4 = cmul(w2, w2);
    float2 w5 = cmul(w4, w1);
    float2 w6 = cmul(w4, w2);
    float2 w7 = cmul(w4, w3);
    float2 w8 = cmul(w4, w4);
    x[1] = cmul(x[1], w1);
    x[2] = cmul(x[2], w2);
    x[3] = cmul(x[3], w3);
    x[4] = cmul(x[4], w4);
    x[5] = cmul(x[5], w5);
    x[6] = cmul(x[6], w6);
    x[7] = cmul(x[7], w7);
    x[8] = cmul(x[8], w8);
    x[9]  = cmul(x[9],  cmul(w8, w1));
    x[10] = cmul(x[10], cmul(w8, w2));
    x[11] = cmul(x[11], cmul(w8, w3));
    x[12] = cmul(x[12], cmul(w8, w4));
    x[13] = cmul(x[13], cmul(w8, w5));
    x[14] = cmul(x[14], cmul(w8, w6));
    x[15] = cmul(x[15], cmul(w8, w7));
}

// Radix-16 stage (NS=16000, m=1000), scalar LDS.64, 1000 butterflies.
template <int DIR, bool TO_GMEM>
__device__ __forceinline__ void stage16(float2* sm, int tid, float* __restrict__ gout) {
    for (int n2 = tid; n2 < 1000; n2 += BT) {
        float2 x[16];
#pragma unroll
        for (int j = 0; j < 16; j++) x[j] = sm[PHI(n2 + j * 1000)];
        float2 w1 = g_tw[n2];
        if constexpr (DIR > 0) w1.y = -w1.y;
        if constexpr (DIR < 0) { dft16<DIR>(x); apply_tw16(x, w1); }
        else                   { apply_tw16(x, w1); dft16<DIR>(x); }
#pragma unroll
        for (int j = 0; j < 16; j++) {
            if constexpr (TO_GMEM) gout[n2 + j * 1000] = x[j].x;
            else sm[PHI(n2 + j * 1000)] = x[j];
        }
    }
}

// Radix-10 stage for NS=1000 / NS=100: two adjacent butterflies per thread
// via float4 (LDS.128). Exactly 800 tasks = BT.
template <int NS, int DIR>
__device__ __forceinline__ void stage10_paired(float2* sm, int tid) {
    constexpr int m = NS / 10;
    constexpr int K = NFFT / NS;
    constexpr int halfm = m / 2;
    int u = tid;
    int blk = u / halfm;
    int h = u - blk * halfm;
    int n2 = 2 * h;
    int base = blk * NS + n2;
    float2 X[20];   // even = butterfly A (n2), odd = butterfly B (n2+1)
#pragma unroll
    for (int j = 0; j < 10; j++) {
        float4 t = *(const float4*)&sm[PHI(base + j * m)];
        X[2 * j]     = make_float2(t.x, t.y);
        X[2 * j + 1] = make_float2(t.z, t.w);
    }
    float2 wa = g_tw[n2 * K];
    float2 wb = g_tw[(n2 + 1) * K];
    if constexpr (DIR > 0) { wa.y = -wa.y; wb.y = -wb.y; }
    if constexpr (DIR < 0) {
        dft10s<DIR, 2>(X);     apply_tw10<2>(X, wa);
        dft10s<DIR, 2>(X + 1); apply_tw10<2>(X + 1, wb);
    } else {
        apply_tw10<2>(X, wa);     dft10s<DIR, 2>(X);
        apply_tw10<2>(X + 1, wb); dft10s<DIR, 2>(X + 1);
    }
#pragma unroll
    for (int j = 0; j < 10; j++) {
        *(float4*)&sm[PHI(base + j * m)] =
            make_float4(X[2 * j].x, X[2 * j].y, X[2 * j + 1].x, X[2 * j + 1].y);
    }
}

__device__ __forceinline__ void pw(float2& A, float2& C, float scale) {
    float2 a = A, c = C;
    float2 Fi = make_float2(a.x + c.x, a.y - c.y);
    float2 Fs = make_float2(a.y + c.y, -(a.x - c.x));
    float2 Z = cmul(Fi, Fs);
    Z.x *= scale; Z.y *= scale;
    A = Z;
    C = make_float2(Z.x, -Z.y);   // if A aliases C, Z is real there -> safe
}

// Fused: forward NS=10 stage + Hermitian pointwise + inverse NS=10 stage,
// entirely in registers on a Hermitian-partner block pair.
__device__ __forceinline__ void fused_mid(float2* sm, int tid) {
    const float scale = 0.25f / (float)NFFT;  // two 0.5 unpack factors + 1/N
    int pk = g_pairs[tid];
    int b  = pk & 0xFFFF;
    int b2 = (pk >> 16) & 0x3FFF;
    bool special = (pk >> 30) & 1;
    int pa = PHI(10 * b);    // 10-complex block never crosses a 100-group
    int pb = PHI(10 * b2);
    float2 xa[10], xb[10];
#pragma unroll
    for (int k = 0; k < 5; k++) {
        float4 t = *(const float4*)&sm[pa + 2 * k];
        xa[2 * k] = make_float2(t.x, t.y); xa[2 * k + 1] = make_float2(t.z, t.w);
        float4 s = *(const float4*)&sm[pb + 2 * k];
        xb[2 * k] = make_float2(s.x, s.y); xb[2 * k + 1] = make_float2(s.z, s.w);
    }
    dft10s<-1, 1>(xa);
    dft10s<-1, 1>(xb);
    if (!special) {
        // p = 10b+t (f = f0+1600t)  <->  q = 10b'+(9-t)  (f' = N-f)
#pragma unroll
        for (int t = 0; t < 10; t++) pw(xa[t], xb[9 - t], scale);
    } else {
        // xa: block f0=0   -> t <-> (10-t)%10 ; t=0,5 self (Z real)
        pw(xa[0], xa[0], scale);
        pw(xa[5], xa[5], scale);
        pw(xa[1], xa[9], scale);
        pw(xa[2], xa[8], scale);
        pw(xa[3], xa[7], scale);
        pw(xa[4], xa[6], scale);
        // xb: block f0=800 -> t <-> 9-t (no self)
        pw(xb[0], xb[9], scale);
        pw(xb[1], xb[8], scale);
        pw(xb[2], xb[7], scale);
        pw(xb[3], xb[6], scale);
        pw(xb[4], xb[5], scale);
    }
    dft10s<1, 1>(xa);
    dft10s<1, 1>(xb);
#pragma unroll
    for (int k = 0; k < 5; k++) {
        *(float4*)&sm[pa + 2 * k] = make_float4(xa[2 * k].x, xa[2 * k].y, xa[2 * k + 1].x, xa[2 * k + 1].y);
        *(float4*)&sm[pb + 2 * k] = make_float4(xb[2 * k].x, xb[2 * k].y, xb[2 * k + 1].x, xb[2 * k + 1].y);
    }
}

__global__ void __launch_bounds__(BT) mcb_main_kernel(
    const float* __restrict__ img, const float* __restrict__ seq,
    const int* __restrict__ hv, const float* __restrict__ sv,
    float* __restrict__ out, int d) {
    extern __shared__ float2 sm[];
    const int b = blockIdx.x;
    const int tid = threadIdx.x;

    float4* sm4 = (float4*)sm;
#pragma unroll 4
    for (int i = tid; i < SMPAD / 2; i += BT) sm4[i] = make_float4(0.f, 0.f, 0.f, 0.f);
    __syncthreads();

    const float* irow = img + (size_t)b * d;
    const float* qrow = seq + (size_t)b * d;
    for (int i = tid; i < d; i += BT) {
        int h = PHI(hv[i]);
        float s = sv[i];
        atomicAdd(&sm[h].x, irow[i] * s);
        atomicAdd(&sm[h].y, qrow[i] * s);
    }
    __syncthreads();

    float* orow = out + (size_t)b * NFFT;

    // forward: 16, 10, 10 | fused(10 + pointwise + 10) | inverse: 10, 10, 16->gmem
    stage16<-1, false>(sm, tid, orow);   __syncthreads();
    stage10_paired<1000, -1>(sm, tid);   __syncthreads();
    stage10_paired<100, -1>(sm, tid);    __syncthreads();
    fused_mid(sm, tid);                  __syncthreads();
    stage10_paired<100, 1>(sm, tid);     __syncthreads();
    stage10_paired<1000, 1>(sm, tid);    __syncthreads();
    stage16<1, true>(sm, tid, orow);
}

extern "C" void kernel_launch(void* const* d_in, const int* in_sizes, int n_in,
                              void* d_out, int out_size) {
    const float* img = (const float*)d_in[0];
    const float* seq = (const float*)d_in[1];
    const int* hv = (const int*)d_in[2];
    const float* sv = (const float*)d_in[3];
    float* out = (float*)d_out;

    int d = in_sizes[2];
    int B = in_sizes[0] / d;

    static_assert(NFFT == 16000, "radix plan assumes N=16000");

    cudaFuncSetAttribute(mcb_main_kernel, cudaFuncAttributeMaxDynamicSharedMemorySize,
                         SMPAD * sizeof(float2));

    init_tables_kernel<<<(NFFT + 255) / 256, 256>>>();
    mcb_main_kernel<<<B, BT, SMPAD * sizeof(float2)>>>(img, seq, hv, sv, out, d);
}

// round 5
// speedup vs baseline: 2.4740x; 1.1071x over previous
#include <cuda_runtime.h>

#define NFFT 16000
#define NH   8000
#define BT   800
// 16000-domain padding (forward stages)
#define PHI(i)  ((i) + 6 * ((i) / 100))
#define SMPAD   (NFFT + 6 * (NFFT / 100))        // 16960 float2
// 8000-domain padding (inverse stages), separate region
#define PHI8(i) ((i) + 3 * ((i) / 50))
#define SMPAD8  (NH + 3 * (NH / 50))             // 8480 float2
#define SMTOTAL ((SMPAD + SMPAD8) * sizeof(float2))  // 203,520 B

// Forward plan (DIF) on 16000: 16,10,10,10 -> strides 1000,100,10,1
//   scrambled p = 1000d0+100d1+10d2+d3 holds f = d0+16d1+160d2+1600d3
//   block b = p/10 (f0 = d0+16d1+160d2); Hermitian partner block(1600-f0), t<->9-t
// Inverse plan (DIT) on 8000:  [16,10,10,5] -> input scrambled p' = 5b + t,
//   C[f0+1600t] at p' = 5*block_of(f0) + t; output natural.

__device__ float2 g_tw[NFFT];   // e^{-2*pi*i*t/16000}

__global__ void init_tables_kernel() {
    int p = blockIdx.x * blockDim.x + threadIdx.x;
    if (p < NFFT) {
        double ang = -2.0 * 3.14159265358979323846 * (double)p / (double)NFFT;
        g_tw[p] = make_float2((float)cos(ang), (float)sin(ang));
    }
}

__device__ __forceinline__ int block_of(int f0) {
    return 100 * (f0 & 15) + 10 * ((f0 >> 4) % 10) + (f0 / 160);
}

__device__ __forceinline__ float2 cadd(float2 a, float2 b) { return make_float2(a.x + b.x, a.y + b.y); }
__device__ __forceinline__ float2 csub(float2 a, float2 b) { return make_float2(a.x - b.x, a.y - b.y); }
__device__ __forceinline__ float2 cmul(float2 a, float2 b) {
    return make_float2(fmaf(a.x, b.x, -a.y * b.y), fmaf(a.x, b.y, a.y * b.x));
}
__device__ __forceinline__ float2 cmulc(float2 a, float cr, float ci) {
    return make_float2(fmaf(a.x, cr, -a.y * ci), fmaf(a.x, ci, a.y * cr));
}
template <int DIR>
__device__ __forceinline__ float2 cmuli(float2 a) {   // * (DIR*i)
    return (DIR > 0) ? make_float2(-a.y, a.x) : make_float2(a.y, -a.x);
}

template <int DIR>
__device__ __forceinline__ void dft4(float2* x) {
    float2 t0 = cadd(x[0], x[2]);
    float2 t1 = csub(x[0], x[2]);
    float2 t2 = cadd(x[1], x[3]);
    float2 t3 = cmuli<DIR>(csub(x[1], x[3]));
    x[0] = cadd(t0, t2);
    x[2] = csub(t0, t2);
    x[1] = cadd(t1, t3);
    x[3] = csub(t1, t3);
}

template <int DIR>
__device__ __forceinline__ void dft5(float2* x) {
    const float c1 = 0.30901699437494742f;
    const float c2 = -0.80901699437494745f;
    const float s1 = 0.95105651629515357f;
    const float s2 = 0.58778525229247313f;
    float2 t1 = cadd(x[1], x[4]);
    float2 t2 = cadd(x[2], x[3]);
    float2 t3 = csub(x[1], x[4]);
    float2 t4 = csub(x[2], x[3]);
    float2 x0 = x[0];
    float2 a1 = make_float2(x0.x + c1 * t1.x + c2 * t2.x, x0.y + c1 * t1.y + c2 * t2.y);
    float2 a2 = make_float2(x0.x + c2 * t1.x + c1 * t2.x, x0.y + c2 * t1.y + c1 * t2.y);
    float2 b1 = make_float2(s1 * t3.x + s2 * t4.x, s1 * t3.y + s2 * t4.y);
    float2 b2 = make_float2(s2 * t3.x - s1 * t4.x, s2 * t3.y - s1 * t4.y);
    x[0] = make_float2(x0.x + t1.x + t2.x, x0.y + t1.y + t2.y);
    float2 ib1 = cmuli<DIR>(b1);
    float2 ib2 = cmuli<DIR>(b2);
    x[1] = cadd(a1, ib1);
    x[4] = csub(a1, ib1);
    x[2] = cadd(a2, ib2);
    x[3] = csub(a2, ib2);
}

// 10-point DFT = 2x5 CT, stride-S register access.
template <int DIR, int S>
__device__ __forceinline__ void dft10s(float2* x) {
    const float C36 = 0.80901699437494742f;
    const float S36 = 0.58778525229247313f;
    const float C72 = 0.30901699437494742f;
    const float S72 = 0.95105651629515357f;
    const float D = (float)DIR;
    float2 a[5], c[5];
#pragma unroll
    for (int k = 0; k < 5; k++) {
        a[k] = cadd(x[k * S], x[(k + 5) * S]);
        c[k] = csub(x[k * S], x[(k + 5) * S]);
    }
    c[1] = cmulc(c[1], C36, D * S36);
    c[2] = cmulc(c[2], C72, D * S72);
    c[3] = cmulc(c[3], -C72, D * S72);
    c[4] = cmulc(c[4], -C36, D * S36);
    dft5<DIR>(a);
    dft5<DIR>(c);
    x[0 * S] = a[0]; x[2 * S] = a[1]; x[4 * S] = a[2]; x[6 * S] = a[3]; x[8 * S] = a[4];
    x[1 * S] = c[0]; x[3 * S] = c[1]; x[5 * S] = c[2]; x[7 * S] = c[3]; x[9 * S] = c[4];
}

// 16-point DFT = 4x4 CT (contiguous).
template <int DIR>
__device__ __forceinline__ void dft16(float2* x) {
    const float C1 = 0.92387953251128674f;
    const float S1 = 0.38268343236508978f;
    const float C2 = 0.70710678118654752f;
    const float D = (float)DIR;
    float2 y[16];
#pragma unroll
    for (int n2 = 0; n2 < 4; n2++) {
        float2 t[4] = {x[n2], x[n2 + 4], x[n2 + 8], x[n2 + 12]};
        dft4<DIR>(t);
        if (n2 == 1) {
            t[1] = cmulc(t[1], C1, D * S1);
            t[2] = cmulc(t[2], C2, D * C2);
            t[3] = cmulc(t[3], S1, D * C1);
        } else if (n2 == 2) {
            t[1] = cmulc(t[1], C2, D * C2);
            t[2] = cmuli<DIR>(t[2]);
            t[3] = cmulc(t[3], -C2, D * C2);
        } else if (n2 == 3) {
            t[1] = cmulc(t[1], S1, D * C1);
            t[2] = cmulc(t[2], -C2, D * C2);
            t[3] = cmulc(t[3], -C1, -D * S1);
        }
        y[0 + n2] = t[0]; y[4 + n2] = t[1]; y[8 + n2] = t[2]; y[12 + n2] = t[3];
    }
#pragma unroll
    for (int k1 = 0; k1 < 4; k1++) {
        float2 t[4] = {y[k1 * 4 + 0], y[k1 * 4 + 1], y[k1 * 4 + 2], y[k1 * 4 + 3]};
        dft4<DIR>(t);
        x[k1 + 0] = t[0]; x[k1 + 4] = t[1]; x[k1 + 8] = t[2]; x[k1 + 12] = t[3];
    }
}

template <int S>
__device__ __forceinline__ void apply_tw10(float2* x, float2 w1) {
    float2 w2 = cmul(w1, w1);
    float2 w3 = cmul(w2, w1);
    float2 w4 = cmul(w2, w2);
    float2 w5 = cmul(w4, w1);
    x[1 * S] = cmul(x[1 * S], w1);
    x[2 * S] = cmul(x[2 * S], w2);
    x[3 * S] = cmul(x[3 * S], w3);
    x[4 * S] = cmul(x[4 * S], w4);
    x[5 * S] = cmul(x[5 * S], w5);
    x[6 * S] = cmul(x[6 * S], cmul(w5, w1));
    x[7 * S] = cmul(x[7 * S], cmul(w5, w2));
    x[8 * S] = cmul(x[8 * S], cmul(w5, w3));
    x[9 * S] = cmul(x[9 * S], cmul(w5, w4));
}

__device__ __forceinline__ void apply_tw16(float2* x, float2 w1) {
    float2 w2 = cmul(w1, w1);
    float2 w3 = cmul(w2, w1);
    float2 w4 = cmul(w2, w2);
    float2 w5 = cmul(w4, w1);
    float2 w6 = cmul(w4, w2);
    float2 w7 = cmul(w4, w3);
    float2 w8 = cmul(w4, w4);
    x[1] = cmul(x[1], w1);
    x[2] = cmul(x[2], w2);
    x[3] = cmul(x[3], w3);
    x[4] = cmul(x[4], w4);
    x[5] = cmul(x[5], w5);
    x[6] = cmul(x[6], w6);
    x[7] = cmul(x[7], w7);
    x[8] = cmul(x[8], w8);
    x[9]  = cmul(x[9],  cmul(w8, w1));
    x[10] = cmul(x[10], cmul(w8, w2));
    x[11] = cmul(x[11], cmul(w8, w3));
    x[12] = cmul(x[12], cmul(w8, w4));
    x[13] = cmul(x[13], cmul(w8, w5));
    x[14] = cmul(x[14], cmul(w8, w6));
    x[15] = cmul(x[15], cmul(w8, w7));
}

// Forward radix-16 stage on 16000 (NS=16000, m=1000), DIF.
__device__ __forceinline__ void stage16_fwd(float2* sm, int tid) {
    for (int n2 = tid; n2 < 1000; n2 += BT) {
        float2 x[16];
#pragma unroll
        for (int j = 0; j < 16; j++) x[j] = sm[PHI(n2 + j * 1000)];
        dft16<-1>(x);
        apply_tw16(x, g_tw[n2]);
#pragma unroll
        for (int j = 0; j < 16; j++) sm[PHI(n2 + j * 1000)] = x[j];
    }
}

// Forward radix-10 stage on 16000, two adjacent butterflies per thread (float4).
template <int NS>
__device__ __forceinline__ void stage10_paired(float2* sm, int tid) {
    constexpr int m = NS / 10;
    constexpr int K = NFFT / NS;
    constexpr int halfm = m / 2;
    int blk = tid / halfm;
    int h = tid - blk * halfm;
    int n2 = 2 * h;
    int base = blk * NS + n2;
    float2 X[20];
#pragma unroll
    for (int j = 0; j < 10; j++) {
        float4 t = *(const float4*)&sm[PHI(base + j * m)];
        X[2 * j]     = make_float2(t.x, t.y);
        X[2 * j + 1] = make_float2(t.z, t.w);
    }
    float2 wa = g_tw[n2 * K];
    float2 wb = g_tw[(n2 + 1) * K];
    dft10s<-1, 2>(X);     apply_tw10<2>(X, wa);
    dft10s<-1, 2>(X + 1); apply_tw10<2>(X + 1, wb);
#pragma unroll
    for (int j = 0; j < 10; j++) {
        *(float4*)&sm[PHI(base + j * m)] =
            make_float4(X[2 * j].x, X[2 * j].y, X[2 * j + 1].x, X[2 * j + 1].y);
    }
}

// Inverse (DIT) stage on the 8000-point array in region s8.
template <int R, int NS, bool TO_GMEM>
__device__ __forceinline__ void stage8_inv(float2* s8, int tid, float2* __restrict__ gout2) {
    constexpr int m = NS / R;
    constexpr int K2 = 2 * (NH / NS);   // index multiplier into g_tw (16000 table)
    constexpr int nb = NH / R;
    for (int u = tid; u < nb; u += BT) {
        int blk = u / m;
        int n2 = u - blk * m;
        int base = blk * NS + n2;
        float2 x[R];
#pragma unroll
        for (int j = 0; j < R; j++) x[j] = s8[PHI8(base + j * m)];
        float2 w1 = g_tw[n2 * K2];
        w1.y = -w1.y;   // conj -> e^{+}
        if constexpr (R == 16) { apply_tw16(x, w1); dft16<1>(x); }
        else                   { apply_tw10<1>(x, w1); dft10s<1, 1>(x); }
#pragma unroll
        for (int j = 0; j < R; j++) {
            if constexpr (TO_GMEM) gout2[base + j * m] = x[j];   // c[n] -> (z[2n], z[2n+1])
            else s8[PHI8(base + j * m)] = x[j];
        }
    }
}

__device__ __forceinline__ void pw(float2& A, float2& C, float scale) {
    float2 a = A, c = C;
    float2 Fi = make_float2(a.x + c.x, a.y - c.y);
    float2 Fs = make_float2(a.y + c.y, -(a.x - c.x));
    float2 Z = cmul(Fi, Fs);
    Z.x *= scale; Z.y *= scale;
    A = Z;
    C = make_float2(Z.x, -Z.y);
}

// Pack Z-block (10 values, f = f0+1600t) into 5 C values of the 8000-domain,
// then first inverse stage (radix-5), store at s8[PHI8(5b + j)].
// C[k] = (Z[k]+Z[k+8000]) + i * e^{+2pi i k/16000} * (Z[k]-Z[k+8000])
// (all constant factors folded into pw's scale)
__device__ __forceinline__ void pack_inv5_store(const float2* x, float2 w0,
                                                float2* s8, int b) {
    // rho_t = e^{+2*pi*i*t/10}
    const float RC[5] = {1.f, 0.80901699437494742f, 0.30901699437494742f,
                         -0.30901699437494742f, -0.80901699437494742f};
    const float RS[5] = {0.f, 0.58778525229247313f, 0.95105651629515357f,
                         0.95105651629515357f, 0.58778525229247313f};
    float2 C[5];
#pragma unroll
    for (int t = 0; t < 5; t++) {
        float2 S = cadd(x[t], x[t + 5]);
        float2 Dd = csub(x[t], x[t + 5]);
        float2 wt = (t == 0) ? w0 : cmul(w0, make_float2(RC[t], RS[t]));
        C[t] = cadd(S, cmuli<1>(cmul(wt, Dd)));
    }
    dft5<1>(C);
    int base = PHI8(5 * b);   // 5b..5b+4 never cross a 50-group (5b%50 <= 45)
#pragma unroll
    for (int j = 0; j < 5; j++) s8[base + j] = C[j];
}

// Fused middle: forward radix-10 (m=1) + Hermitian pointwise + pack to 8000-domain
// + inverse radix-5 (m=1), entirely in registers on a Hermitian block pair.
__device__ __forceinline__ void fused_mid(float2* sm, float2* s8, int tid) {
    const float scale = 0.25f / (float)NFFT;  // unpack(1/4) * pack(1/2) * ifft(1/8000) = 0.25/16000
    int fa, fb;
    if (tid < 799) { fa = tid + 1; fb = 1600 - fa; }
    else           { fa = 0;       fb = 800; }
    int b  = block_of(fa);
    int b2 = block_of(fb);
    int pa = PHI(10 * b);
    int pb = PHI(10 * b2);
    float2 xa[10], xb[10];
#pragma unroll
    for (int k = 0; k < 5; k++) {
        float4 t = *(const float4*)&sm[pa + 2 * k];
        xa[2 * k] = make_float2(t.x, t.y); xa[2 * k + 1] = make_float2(t.z, t.w);
        float4 s = *(const float4*)&sm[pb + 2 * k];
        xb[2 * k] = make_float2(s.x, s.y); xb[2 * k + 1] = make_float2(s.z, s.w);
    }
    dft10s<-1, 1>(xa);
    dft10s<-1, 1>(xb);
    if (tid < 799) {
#pragma unroll
        for (int t = 0; t < 10; t++) pw(xa[t], xb[9 - t], scale);
    } else {
        pw(xa[0], xa[0], scale);
        pw(xa[5], xa[5], scale);
        pw(xa[1], xa[9], scale);
        pw(xa[2], xa[8], scale);
        pw(xa[3], xa[7], scale);
        pw(xa[4], xa[6], scale);
        pw(xb[0], xb[9], scale);
        pw(xb[1], xb[8], scale);
        pw(xb[2], xb[7], scale);
        pw(xb[3], xb[6], scale);
        pw(xb[4], xb[5], scale);
    }
    float2 ta = g_tw[fa]; ta.y = -ta.y;   // e^{+2pi i fa/16000}
    float2 tb = g_tw[fb]; tb.y = -tb.y;
    pack_inv5_store(xa, ta, s8, b);
    pack_inv5_store(xb, tb, s8, b2);
}

__global__ void __launch_bounds__(BT) mcb_main_kernel(
    const float* __restrict__ img, const float* __restrict__ seq,
    const int* __restrict__ hv, const float* __restrict__ sv,
    float* __restrict__ out, int d) {
    extern __shared__ float2 sm[];
    float2* s8 = sm + SMPAD;
    const int b = blockIdx.x;
    const int tid = threadIdx.x;

    float4* sm4 = (float4*)sm;
#pragma unroll 4
    for (int i = tid; i < SMPAD / 2; i += BT) sm4[i] = make_float4(0.f, 0.f, 0.f, 0.f);
    __syncthreads();

    const float* irow = img + (size_t)b * d;
    const float* qrow = seq + (size_t)b * d;
    for (int i = tid; i < d; i += BT) {
        int h = PHI(hv[i]);
        float s = sv[i];
        atomicAdd(&sm[h].x, irow[i] * s);
        atomicAdd(&sm[h].y, qrow[i] * s);
    }
    __syncthreads();

    float2* orow2 = (float2*)(out + (size_t)b * NFFT);

    // forward 16000: 16, 10, 10 | fused(10 + pointwise + pack + inv5)
    stage16_fwd(sm, tid);             __syncthreads();
    stage10_paired<1000>(sm, tid);    __syncthreads();
    stage10_paired<100>(sm, tid);     __syncthreads();
    fused_mid(sm, s8, tid);           __syncthreads();
    // inverse 8000: 10 (m=5), 10 (m=50), 16 (m=500) -> gmem float2
    stage8_inv<10, 50, false>(s8, tid, orow2);   __syncthreads();
    stage8_inv<10, 500, false>(s8, tid, orow2);  __syncthreads();
    stage8_inv<16, 8000, true>(s8, tid, orow2);
}

extern "C" void kernel_launch(void* const* d_in, const int* in_sizes, int n_in,
                              void* d_out, int out_size) {
    const float* img = (const float*)d_in[0];
    const float* seq = (const float*)d_in[1];
    const int* hv = (const int*)d_in[2];
    const float* sv = (const float*)d_in[3];
    float* out = (float*)d_out;

    int d = in_sizes[2];
    int B = in_sizes[0] / d;

    static_assert(NFFT == 16000 && NH == 8000, "plan assumes N=16000");

    cudaFuncSetAttribute(mcb_main_kernel, cudaFuncAttributeMaxDynamicSharedMemorySize,
                         SMTOTAL);

    init_tables_kernel<<<(NFFT + 255) / 256, 256>>>();
    mcb_main_kernel<<<B, BT, SMTOTAL>>>(img, seq, hv, sv, out, d);
}